// round 13
// baseline (speedup 1.0000x reference)
#include <cuda_runtime.h>
#include <cuda_fp16.h>
#include <cstdint>

#define T_  512
#define B_  128
#define D_  128
#define H_  512
#define O_  128
#define G4H 2048
#define NL  64
#define NCTA 128

#define HPAD 136
#define ROWB 272
#define CHB  34816     // one 128-k chunk: 128 rows x 272 B

// ---------------- static device buffers ----------------
__device__ __align__(16) __half g_xTT[T_ * D_ * HPAD];         // [t][d][b]
__device__ __align__(16) __half g_h0T[4 * H_ * HPAD];          // ring [slot][k][b]
__device__ __align__(16) __half g_h1T[(T_ + 1) * H_ * HPAD];   // [t][k][b]
__device__ __align__(16) __half g_h1seq[(T_ + 1) * B_ * H_];   // [t][b][k] (for out proj)
__device__ __align__(16) __half g_W0[G4H * 640];
__device__ __align__(16) __half g_W1[G4H * 1024];
__device__ __align__(16) __half g_Wout[O_ * H_];
__device__ __align__(16) float  g_cS[NCTA * B_ * 8];           // per-CTA cell state [r][col8]
__device__ unsigned g_c0g[4], g_c1g[4];   // per-k-group completion counters (x16 CTAs)
__device__ unsigned g_cnt1;               // coarse layer-1 counter (ring guard)

// ---------------- SMEM layout (recur) ----------------
#define B_OFF     139264
#define BCHUNK_SZ 4608
#define HST_OFF   212992
#define MB_OFF    215168
#define RED_OFF   215232       // 16 KB split-K partial buffer
#define SMEM_LSTM 231616

// ---------------- PTX helpers ----------------
__device__ __forceinline__ void mma_f16(float* c, const uint32_t* a, const uint32_t* b) {
    asm volatile("mma.sync.aligned.m16n8k16.row.col.f32.f16.f16.f32 "
        "{%0,%1,%2,%3}, {%4,%5,%6,%7}, {%8,%9}, {%0,%1,%2,%3};"
        : "+f"(c[0]), "+f"(c[1]), "+f"(c[2]), "+f"(c[3])
        : "r"(a[0]), "r"(a[1]), "r"(a[2]), "r"(a[3]), "r"(b[0]), "r"(b[1]));
}
__device__ __forceinline__ void ldsm4(uint32_t* r, uint32_t a) {
    asm volatile("ldmatrix.sync.aligned.m8n8.x4.shared.b16 {%0,%1,%2,%3}, [%4];"
                 : "=r"(r[0]), "=r"(r[1]), "=r"(r[2]), "=r"(r[3]) : "r"(a));
}
__device__ __forceinline__ void ldsm4t(uint32_t* r, uint32_t a) {
    asm volatile("ldmatrix.sync.aligned.m8n8.x4.trans.shared.b16 {%0,%1,%2,%3}, [%4];"
                 : "=r"(r[0]), "=r"(r[1]), "=r"(r[2]), "=r"(r[3]) : "r"(a));
}
__device__ __forceinline__ void mbar_init(uint32_t a, uint32_t c) {
    asm volatile("mbarrier.init.shared.b64 [%0], %1;" :: "r"(a), "r"(c) : "memory");
}
__device__ __forceinline__ void mbar_wait(uint32_t a, uint32_t par) {
    uint32_t done;
    asm volatile("{\n\t.reg .pred p;\n\tmbarrier.try_wait.parity.acquire.cta.shared::cta.b64 p, [%1], %2;\n\tselp.b32 %0, 1, 0, p;\n\t}"
                 : "=r"(done) : "r"(a), "r"(par) : "memory");
    if (!done) {
        asm volatile("{\n\t.reg .pred P1;\n\tWL%=:\n\tmbarrier.try_wait.parity.acquire.cta.shared::cta.b64 P1, [%0], %1, 0x989680;\n\t@P1 bra.uni WD%=;\n\tbra.uni WL%=;\n\tWD%=:\n\t}"
                     :: "r"(a), "r"(par) : "memory");
    }
}
__device__ __forceinline__ void mbar_expect(uint32_t a, uint32_t tx) {
    asm volatile("mbarrier.arrive.expect_tx.shared.b64 _, [%0], %1;" :: "r"(a), "r"(tx) : "memory");
}
__device__ __forceinline__ void mbar_arrive(uint32_t a) {
    asm volatile("mbarrier.arrive.shared.b64 _, [%0];" :: "r"(a) : "memory");
}
__device__ __forceinline__ void bulk_g2s(uint32_t sdst, const void* g, uint32_t bytes, uint32_t mb) {
    asm volatile("cp.async.bulk.shared::cluster.global.mbarrier::complete_tx::bytes [%0], [%1], %2, [%3];"
                 :: "r"(sdst), "l"(g), "r"(bytes), "r"(mb) : "memory");
}
__device__ __forceinline__ void fence_pa() { asm volatile("fence.proxy.async.shared::cta;" ::: "memory"); }
__device__ __forceinline__ unsigned ld_acq(const unsigned* p) {
    unsigned v; asm volatile("ld.acquire.gpu.global.u32 %0, [%1];" : "=r"(v) : "l"(p)); return v;
}
__device__ __forceinline__ void wait_cnt(const unsigned* p, unsigned tgt) { while (ld_acq(p) < tgt) { } }
__device__ __forceinline__ void arrive_cnt(unsigned* p) {
    asm volatile("red.release.gpu.global.add.u32 [%0], 1;" :: "l"(p) : "memory");
}
__device__ __forceinline__ void bsync(int id, int cnt) {
    asm volatile("bar.sync %0, %1;" :: "r"(id), "r"(cnt) : "memory");
}
__device__ __forceinline__ void barr(int id, int cnt) {
    asm volatile("bar.arrive %0, %1;" :: "r"(id), "r"(cnt) : "memory");
}
__device__ __forceinline__ float sigf(float x)  { return __fdividef(1.0f, 1.0f + __expf(-x)); }
__device__ __forceinline__ float tanhe(float x) { return __fdividef(2.0f, 1.0f + __expf(-2.0f * x)) - 1.0f; }

// ---------------- prep kernels ----------------
__global__ void __launch_bounds__(256) lstm86_prep(
    const float* __restrict__ h0,
    const float* __restrict__ wih0, const float* __restrict__ whh0,
    const float* __restrict__ wih1, const float* __restrict__ whh1,
    const float* __restrict__ wout)
{
    const int tid = blockIdx.x * blockDim.x + threadIdx.x;
    const int nt  = gridDim.x * blockDim.x;
    for (int i = tid; i < G4H * 640; i += nt) {
        int n = i / 640, k = i - n * 640;
        g_W0[i] = __float2half((k < 128) ? wih0[n * 128 + k] : whh0[n * 512 + (k - 128)]);
    }
    for (int i = tid; i < G4H * 1024; i += nt) {
        int n = i >> 10, k = i & 1023;
        g_W1[i] = __float2half((k < 512) ? wih1[n * 512 + k] : whh1[n * 512 + (k - 512)]);
    }
    for (int i = tid; i < O_ * H_; i += nt) g_Wout[i] = __float2half(wout[i]);
    for (int i = tid; i < B_ * H_; i += nt) {
        int b = i >> 9, k = i & 511;
        g_h0T[3 * H_ * HPAD + k * HPAD + b] = __float2half(h0[b * H_ + k]);
        g_h1T[k * HPAD + b]                 = __float2half(h0[B_ * H_ + b * H_ + k]);
    }
    if (tid < 4) { g_c0g[tid] = 0; g_c1g[tid] = 0; }
    if (tid == 4) g_cnt1 = 0;
}

__global__ void __launch_bounds__(256) lstm86_prepx(const float* __restrict__ x)
{
    __shared__ __half sm[128 * 136];
    const int t = blockIdx.x, tid = threadIdx.x;
    for (int i = tid; i < B_ * D_; i += 256) {
        int b = i >> 7, d = i & 127;
        sm[d * 136 + b] = __float2half(x[(size_t)b * (T_ * D_) + t * D_ + d]);
    }
    __syncthreads();
    for (int i = tid; i < 128 * 16; i += 256) {
        int d = i >> 4, seg = i & 15;
        *(uint4*)&g_xTT[(size_t)t * D_ * HPAD + d * HPAD + seg * 8] = *(uint4*)&sm[d * 136 + seg * 8];
    }
}

// ---------------- persistent recurrent kernel ----------------
template <int LAYER>
__device__ void lstm86_role(int q, const float* __restrict__ c0, char* smem)
{
    constexpr int K  = (LAYER == 0) ? 640 : 1024;
    constexpr int NC = (LAYER == 0) ? 5 : 8;     // 128-k chunks
    const int tid  = threadIdx.x;
    const int warp = tid >> 5, lane = tid & 31;
    const int cta  = LAYER * NL + q;
    const uint32_t sb = (uint32_t)__cvta_generic_to_shared(smem);
    const uint32_t MB = sb + MB_OFF;

    if (tid == 0) {
        #pragma unroll
        for (int st = 0; st < 4; st++) { mbar_init(MB + st * 16, 1); mbar_init(MB + st * 16 + 8, 256); }
        fence_pa();
    }
    // resident weights: [kc64][32 n][144 B]; local n = gate*8 + jj
    {
        const __half* Wg = (LAYER == 0) ? g_W0 : g_W1;
        for (int i = tid; i < (K / 64) * 256; i += 288) {
            int kc = i >> 8, rem = i & 255, n = rem >> 3, sg = rem & 7;
            int ng = (n >> 3) * 512 + q * 8 + (n & 7);
            *(uint4*)(smem + B_OFF + kc * BCHUNK_SZ + n * 144 + sg * 16) =
                *(const uint4*)&Wg[(size_t)ng * K + kc * 64 + sg * 8];
        }
    }
    // cell-state prefill: g_cS[cta][r*8+col] = c0[...]
    for (int i = tid; i < B_ * 8; i += 288) {
        int r = i >> 3, col = i & 7;
        g_cS[(size_t)cta * (B_ * 8) + i] = c0[LAYER * B_ * H_ + (size_t)r * H_ + q * 8 + col];
    }
    __syncthreads();   // last full-block sync

    // ================= producer warp (warp 8) =================
    if (warp == 8) {
        if (tid == 256) {
            int igi = 0;
            for (int t = 0; t < T_; t++) {
                for (int i = 0; i < NC; i++) {
                    if (LAYER == 0) {
                        if (i >= 1 && t > 0) wait_cnt(&g_c0g[i - 1], 16u * (unsigned)t);
                    } else {
                        if (i < 4) wait_cnt(&g_c0g[i], 16u * (unsigned)(t + 1));
                        else if (t > 0) wait_cnt(&g_c1g[i - 4], 16u * (unsigned)t);
                    }
                    int st = igi & 3;
                    if (igi >= 4) mbar_wait(MB + st * 16 + 8, (unsigned)((igi - 4) >> 2) & 1);
                    const __half* src;
                    if (LAYER == 0)
                        src = (i == 0) ? g_xTT + (size_t)t * D_ * HPAD
                                       : g_h0T + (size_t)((t + 3) & 3) * H_ * HPAD + (size_t)(i - 1) * 128 * HPAD;
                    else
                        src = (i < 4) ? g_h0T + (size_t)(t & 3) * H_ * HPAD + (size_t)i * 128 * HPAD
                                      : g_h1T + (size_t)t * H_ * HPAD + (size_t)(i - 4) * 128 * HPAD;
                    mbar_expect(MB + st * 16, CHB);
                    bulk_g2s(sb + (uint32_t)st * CHB, src, CHB, MB + st * 16);
                    igi++;
                }
            }
        }
        return;
    }

    // ================= consumer warps (0-7): split-K, m32 x n32 each =================
    const int km  = warp >> 2;        // k-half of each chunk
    const int wm4 = warp & 3;         // m-tile id
    const uint32_t a_krow = (uint32_t)((lane & 7) + ((lane >> 4) & 1) * 8);
    const uint32_t a_col  = (uint32_t)(wm4 * 32 + ((lane >> 3) & 1) * 8);
    const uint32_t b_row  = (uint32_t)(((lane >> 4) & 1) * 8 + (lane & 7));
    const uint32_t b_koff = (uint32_t)(((lane >> 3) & 1) * 8);

    const int rrow0 = wm4 * 32 + (lane >> 2);
    const int jcol  = q * 8 + (lane & 3) * 2;
    float* cS = g_cS + (size_t)cta * (B_ * 8);

    float* red = (float*)(smem + RED_OFF);
    int cgi = 0;
    for (int t = 0; t < T_; t++) {
        float acc[2][4][4];
        #pragma unroll
        for (int mi = 0; mi < 2; mi++)
            #pragma unroll
            for (int n8 = 0; n8 < 4; n8++)
                #pragma unroll
                for (int r = 0; r < 4; r++) acc[mi][n8][r] = 0.0f;

        for (int j = 0; j < NC; j++) {
            int st = cgi & 3;
            mbar_wait(MB + st * 16, (unsigned)(cgi >> 2) & 1);
            cgi++;
            const uint32_t SA = sb + (uint32_t)st * CHB;
            const int kcb = (LAYER == 0) ? 2 * j : ((j < 4) ? 2 * j : 8 + 2 * (j - 4));
            const uint32_t BC = sb + B_OFF + (uint32_t)(kcb + km) * BCHUNK_SZ;
            #pragma unroll
            for (int kk = 0; kk < 4; kk++) {
                int kke = km * 4 + kk;
                uint32_t a0[4], a1[4], b0[4], b1[4];
                uint32_t krow = (uint32_t)(kke * 16) + a_krow;
                ldsm4t(a0, SA + krow * ROWB + a_col * 2);
                ldsm4t(a1, SA + krow * ROWB + (a_col + 16) * 2);
                uint32_t kb = (uint32_t)kk * 32;
                ldsm4(b0, BC + b_row * 144 + kb + b_koff * 2);
                ldsm4(b1, BC + (b_row + 16) * 144 + kb + b_koff * 2);
                mma_f16(acc[0][0], a0, b0);  mma_f16(acc[0][1], a0, b0 + 2);
                mma_f16(acc[0][2], a0, b1);  mma_f16(acc[0][3], a0, b1 + 2);
                mma_f16(acc[1][0], a1, b0);  mma_f16(acc[1][1], a1, b0 + 2);
                mma_f16(acc[1][2], a1, b1);  mma_f16(acc[1][3], a1, b1 + 2);
            }
            mbar_arrive(MB + st * 16 + 8);
        }

        // ---- alternating epilogue: group (km == t&1) reduces + does epilogue; other publishes & runs ahead ----
        const int e = t & 1;
        if (km != e) {
            // publisher: red buffer is free (we consumed it at t-1 as epi, or t==0)
            if (t > 0) bsync(3, 256);
            #pragma unroll
            for (int ee = 0; ee < 32; ee++)
                red[ee * 128 + wm4 * 32 + lane] = acc[ee >> 4][(ee >> 2) & 3][ee & 3];
            barr(2, 256);                    // partials ready; continue to next tick
        } else {
            bsync(2, 256);                   // wait partials (also orders prev epi's c/hs writes)
            // prefetch cell state (global; latency hides under the reduce)
            float cv[2][2][2];
            #pragma unroll
            for (int mi = 0; mi < 2; mi++)
                #pragma unroll
                for (int hf = 0; hf < 2; hf++) {
                    int r = rrow0 + mi * 16 + hf * 8;
                    float2 c2 = *(const float2*)&cS[r * 8 + (lane & 3) * 2];
                    cv[mi][hf][0] = c2.x; cv[mi][hf][1] = c2.y;
                }
            #pragma unroll
            for (int ee = 0; ee < 32; ee++)
                acc[ee >> 4][(ee >> 2) & 3][ee & 3] += red[ee * 128 + wm4 * 32 + lane];

            __half* hs = (__half*)(smem + HST_OFF);
            #pragma unroll
            for (int mi = 0; mi < 2; mi++)
                #pragma unroll
                for (int hf = 0; hf < 2; hf++) {
                    int r = rrow0 + mi * 16 + hf * 8;
                    float h2[2], cn2[2];
                    #pragma unroll
                    for (int cs = 0; cs < 2; cs++) {
                        float gi = acc[mi][0][hf * 2 + cs];
                        float gf = acc[mi][1][hf * 2 + cs];
                        float gg = acc[mi][2][hf * 2 + cs];
                        float go = acc[mi][3][hf * 2 + cs];
                        float cn = sigf(gf) * cv[mi][hf][cs] + sigf(gi) * tanhe(gg);
                        cn2[cs] = cn;
                        h2[cs] = sigf(go) * tanhe(cn);
                        hs[((lane & 3) * 2 + cs) * HPAD + r] = __float2half(h2[cs]);
                    }
                    *(float2*)&cS[r * 8 + (lane & 3) * 2] = make_float2(cn2[0], cn2[1]);
                    if (LAYER == 1) {
                        __half2 p = __floats2half2_rn(h2[0], h2[1]);
                        *(__half2*)(g_h1seq + (size_t)(t + 1) * (B_ * H_) + (size_t)r * H_ + jcol) = p;
                    }
                }
            if (LAYER == 0 && t >= 4 && tid == km * 128) wait_cnt(&g_cnt1, 64u * (unsigned)(t - 3));  // ring guard
            bsync(4 + km, 128);
            {
                int gtid = tid - km * 128;
                int jl = gtid >> 4, sg = gtid & 15;
                __half* dst = ((LAYER == 0) ? g_h0T + (size_t)(t & 3) * H_ * HPAD
                                            : g_h1T + (size_t)(t + 1) * H_ * HPAD)
                              + (size_t)(q * 8 + jl) * HPAD + sg * 8;
                *(uint4*)dst = *(uint4*)(smem + HST_OFF + jl * ROWB + sg * 16);
            }
            bsync(4 + km, 128);
            if (tid == km * 128) {
                if (LAYER == 0) arrive_cnt(&g_c0g[q >> 4]);
                else            { arrive_cnt(&g_c1g[q >> 4]); arrive_cnt(&g_cnt1); }
            }
            barr(3, 256);                    // epilogue done: red/c/hs free for next tick
        }
    }
}

__global__ void __launch_bounds__(288, 1) lstm86_recur(const float* __restrict__ c0)
{
    extern __shared__ char smem[];
    if (blockIdx.x < NL) lstm86_role<0>(blockIdx.x, c0, smem);
    else                 lstm86_role<1>(blockIdx.x - NL, c0, smem);
}

// ---------------- output projection (verified R3 version) ----------------
__global__ void __launch_bounds__(256, 1) lstm86_out(const float* __restrict__ b_out,
                                                     float* __restrict__ out)
{
    extern __shared__ char smem[];
    __half* Ws    = (__half*)smem;
    __half* Ab    = (__half*)(smem + 128 * 520 * 2);
    float*  biasS = (float*)(smem + 128 * 520 * 2 + 2 * 128 * 72 * 2);

    const int t = blockIdx.x;
    const int tid = threadIdx.x, warp = tid >> 5, lane = tid & 31;
    const int wm = warp >> 1, wn = warp & 1;

    for (int i = tid; i < 128 * 64; i += 256) {
        int n = i >> 6, v = i & 63;
        *(uint4*)&Ws[n * 520 + v * 8] = *(const uint4*)&g_Wout[n * 512 + v * 8];
    }
    for (int i = tid; i < 128; i += 256) biasS[i] = b_out[i];
    __syncthreads();

    const __half* Asrc = g_h1seq + (size_t)(t + 1) * (B_ * H_);

    float acc[2][8][4];
    #pragma unroll
    for (int mi = 0; mi < 2; mi++)
        #pragma unroll
        for (int ni = 0; ni < 8; ni++)
            #pragma unroll
            for (int r = 0; r < 4; r++) acc[mi][ni][r] = 0.0f;

    auto load_chunk = [&](int c) {
        __half* dst = Ab + (c & 1) * (128 * 72);
        #pragma unroll
        for (int j = 0; j < 4; j++) {
            int i = tid + j * 256;
            int row = i >> 3, seg = i & 7;
            uint32_t sa = (uint32_t)__cvta_generic_to_shared(dst + row * 72 + seg * 8);
            asm volatile("cp.async.cg.shared.global [%0], [%1], 16;"
                         :: "r"(sa), "l"(Asrc + (size_t)row * H_ + c * 64 + seg * 8));
        }
        asm volatile("cp.async.commit_group;");
    };

    load_chunk(0);
    for (int c = 0; c < 8; c++) {
        if (c < 7) { load_chunk(c + 1); asm volatile("cp.async.wait_group 1;"); }
        else       { asm volatile("cp.async.wait_group 0;"); }
        __syncthreads();
        const __half* A = Ab + (c & 1) * (128 * 72);
        #pragma unroll
        for (int kk = 0; kk < 4; kk++) {
            uint32_t af[2][4], bf2[8][2];
            #pragma unroll
            for (int mi = 0; mi < 2; mi++) {
                int r = wm * 32 + mi * 16 + (lane >> 2);
                int ci = kk * 16 + (lane & 3) * 2;
                af[mi][0] = *(const uint32_t*)&A[r * 72 + ci];
                af[mi][1] = *(const uint32_t*)&A[(r + 8) * 72 + ci];
                af[mi][2] = *(const uint32_t*)&A[r * 72 + ci + 8];
                af[mi][3] = *(const uint32_t*)&A[(r + 8) * 72 + ci + 8];
            }
            #pragma unroll
            for (int ni = 0; ni < 8; ni++) {
                int n  = wn * 64 + ni * 8 + (lane >> 2);
                int kg = c * 64 + kk * 16 + (lane & 3) * 2;
                bf2[ni][0] = *(const uint32_t*)&Ws[n * 520 + kg];
                bf2[ni][1] = *(const uint32_t*)&Ws[n * 520 + kg + 8];
            }
            #pragma unroll
            for (int mi = 0; mi < 2; mi++)
                #pragma unroll
                for (int ni = 0; ni < 8; ni++)
                    mma_f16(acc[mi][ni], af[mi], bf2[ni]);
        }
        __syncthreads();
    }

    #pragma unroll
    for (int mi = 0; mi < 2; mi++)
        #pragma unroll
        for (int ni = 0; ni < 8; ni++) {
            int r  = wm * 32 + mi * 16 + (lane >> 2);
            int co = wn * 64 + ni * 8 + (lane & 3) * 2;
            float b0 = biasS[co], b1 = biasS[co + 1];
            size_t o0 = (size_t)r * (T_ * O_) + (size_t)t * O_ + co;
            size_t o1 = (size_t)(r + 8) * (T_ * O_) + (size_t)t * O_ + co;
            *(float2*)&out[o0] = make_float2(acc[mi][ni][0] + b0, acc[mi][ni][1] + b1);
            *(float2*)&out[o1] = make_float2(acc[mi][ni][2] + b0, acc[mi][ni][3] + b1);
        }
}

#define SMEM_OUT (128 * 520 * 2 + 2 * 128 * 72 * 2 + 128 * 4)

extern "C" void kernel_launch(void* const* d_in, const int* in_sizes, int n_in,
                              void* d_out, int out_size)
{
    const float* x    = (const float*)d_in[0];
    const float* h0   = (const float*)d_in[1];
    const float* c0   = (const float*)d_in[2];
    const float* wih0 = (const float*)d_in[3];
    const float* whh0 = (const float*)d_in[4];
    const float* wih1 = (const float*)d_in[5];
    const float* whh1 = (const float*)d_in[6];
    const float* wout = (const float*)d_in[7];
    const float* bout = (const float*)d_in[8];

    cudaFuncSetAttribute(lstm86_recur, cudaFuncAttributeMaxDynamicSharedMemorySize, SMEM_LSTM);
    cudaFuncSetAttribute(lstm86_out,   cudaFuncAttributeMaxDynamicSharedMemorySize, SMEM_OUT);

    lstm86_prep<<<1024, 256>>>(h0, wih0, whh0, wih1, whh1, wout);
    lstm86_prepx<<<T_, 256>>>(x);
    lstm86_recur<<<NCTA, 288, SMEM_LSTM>>>(c0);
    lstm86_out<<<T_, 256, SMEM_OUT>>>(bout, (float*)d_out);
}

// round 14
// speedup vs baseline: 1.0813x; 1.0813x over previous
#include <cuda_runtime.h>
#include <cuda_fp16.h>
#include <cstdint>

#define T_  512
#define B_  128
#define D_  128
#define H_  512
#define O_  128
#define G4H 2048
#define NL  64
#define NCTA 128

#define HPAD 136
#define ROWB 272
#define CHB  34816     // one 128-k chunk: 128 rows x 272 B

// ---------------- static device buffers ----------------
__device__ __align__(16) __half g_xTT[T_ * D_ * HPAD];         // [t][d][b]
__device__ __align__(16) __half g_h0T[4 * H_ * HPAD];          // ring [slot][k][b]
__device__ __align__(16) __half g_h1T[(T_ + 1) * H_ * HPAD];   // [t][k][b]
__device__ __align__(16) __half g_h1seq[(T_ + 1) * B_ * H_];   // [t][b][k] (for out proj)
__device__ __align__(16) __half g_W0[G4H * 640];
__device__ __align__(16) __half g_W1[G4H * 1024];
__device__ __align__(16) __half g_Wout[O_ * H_];
__device__ unsigned g_c0g[4], g_c1g[4];   // per-k-group completion counters (x16 CTAs)
__device__ unsigned g_cnt1;               // coarse layer-1 counter (ring guard + out-proj signal)

// ---------------- SMEM layout (recur) ----------------
#define B_OFF     139264
#define BCHUNK_SZ 4608
#define HST_OFF   212992
#define MB_OFF    215168
#define RED_OFF   215232       // 16 KB split-K partial buffer
#define SMEM_LSTM 231616

// ---------------- PTX helpers ----------------
__device__ __forceinline__ void mma_f16(float* c, const uint32_t* a, const uint32_t* b) {
    asm volatile("mma.sync.aligned.m16n8k16.row.col.f32.f16.f16.f32 "
        "{%0,%1,%2,%3}, {%4,%5,%6,%7}, {%8,%9}, {%0,%1,%2,%3};"
        : "+f"(c[0]), "+f"(c[1]), "+f"(c[2]), "+f"(c[3])
        : "r"(a[0]), "r"(a[1]), "r"(a[2]), "r"(a[3]), "r"(b[0]), "r"(b[1]));
}
__device__ __forceinline__ void ldsm4(uint32_t* r, uint32_t a) {
    asm volatile("ldmatrix.sync.aligned.m8n8.x4.shared.b16 {%0,%1,%2,%3}, [%4];"
                 : "=r"(r[0]), "=r"(r[1]), "=r"(r[2]), "=r"(r[3]) : "r"(a));
}
__device__ __forceinline__ void ldsm4t(uint32_t* r, uint32_t a) {
    asm volatile("ldmatrix.sync.aligned.m8n8.x4.trans.shared.b16 {%0,%1,%2,%3}, [%4];"
                 : "=r"(r[0]), "=r"(r[1]), "=r"(r[2]), "=r"(r[3]) : "r"(a));
}
__device__ __forceinline__ void mbar_init(uint32_t a, uint32_t c) {
    asm volatile("mbarrier.init.shared.b64 [%0], %1;" :: "r"(a), "r"(c) : "memory");
}
__device__ __forceinline__ void mbar_wait(uint32_t a, uint32_t par) {
    uint32_t done;
    asm volatile("{\n\t.reg .pred p;\n\tmbarrier.try_wait.parity.acquire.cta.shared::cta.b64 p, [%1], %2;\n\tselp.b32 %0, 1, 0, p;\n\t}"
                 : "=r"(done) : "r"(a), "r"(par) : "memory");
    if (!done) {
        asm volatile("{\n\t.reg .pred P1;\n\tWL%=:\n\tmbarrier.try_wait.parity.acquire.cta.shared::cta.b64 P1, [%0], %1, 0x989680;\n\t@P1 bra.uni WD%=;\n\tbra.uni WL%=;\n\tWD%=:\n\t}"
                     :: "r"(a), "r"(par) : "memory");
    }
}
__device__ __forceinline__ void mbar_expect(uint32_t a, uint32_t tx) {
    asm volatile("mbarrier.arrive.expect_tx.shared.b64 _, [%0], %1;" :: "r"(a), "r"(tx) : "memory");
}
__device__ __forceinline__ void mbar_arrive(uint32_t a) {
    asm volatile("mbarrier.arrive.shared.b64 _, [%0];" :: "r"(a) : "memory");
}
__device__ __forceinline__ void bulk_g2s(uint32_t sdst, const void* g, uint32_t bytes, uint32_t mb) {
    asm volatile("cp.async.bulk.shared::cluster.global.mbarrier::complete_tx::bytes [%0], [%1], %2, [%3];"
                 :: "r"(sdst), "l"(g), "r"(bytes), "r"(mb) : "memory");
}
__device__ __forceinline__ void fence_pa() { asm volatile("fence.proxy.async.shared::cta;" ::: "memory"); }
__device__ __forceinline__ unsigned ld_acq(const unsigned* p) {
    unsigned v; asm volatile("ld.acquire.gpu.global.u32 %0, [%1];" : "=r"(v) : "l"(p)); return v;
}
__device__ __forceinline__ void wait_cnt(const unsigned* p, unsigned tgt) { while (ld_acq(p) < tgt) { } }
__device__ __forceinline__ void wait_cnt_sleep(const unsigned* p, unsigned tgt) {
    while (ld_acq(p) < tgt) { __nanosleep(256); }
}
__device__ __forceinline__ void arrive_cnt(unsigned* p) {
    asm volatile("red.release.gpu.global.add.u32 [%0], 1;" :: "l"(p) : "memory");
}
__device__ __forceinline__ void barc() {   // consumer-only barrier (threads 0..255)
    asm volatile("bar.sync 1, 256;" ::: "memory");
}
__device__ __forceinline__ float sigf(float x)  { return __fdividef(1.0f, 1.0f + __expf(-x)); }
__device__ __forceinline__ float tanhe(float x) { return __fdividef(2.0f, 1.0f + __expf(-2.0f * x)) - 1.0f; }

// ---------------- prep kernels ----------------
__global__ void __launch_bounds__(256) lstm86_prep(
    const float* __restrict__ h0,
    const float* __restrict__ wih0, const float* __restrict__ whh0,
    const float* __restrict__ wih1, const float* __restrict__ whh1,
    const float* __restrict__ wout)
{
    const int tid = blockIdx.x * blockDim.x + threadIdx.x;
    const int nt  = gridDim.x * blockDim.x;
    for (int i = tid; i < G4H * 640; i += nt) {
        int n = i / 640, k = i - n * 640;
        g_W0[i] = __float2half((k < 128) ? wih0[n * 128 + k] : whh0[n * 512 + (k - 128)]);
    }
    for (int i = tid; i < G4H * 1024; i += nt) {
        int n = i >> 10, k = i & 1023;
        g_W1[i] = __float2half((k < 512) ? wih1[n * 512 + k] : whh1[n * 512 + (k - 512)]);
    }
    for (int i = tid; i < O_ * H_; i += nt) g_Wout[i] = __float2half(wout[i]);
    for (int i = tid; i < B_ * H_; i += nt) {
        int b = i >> 9, k = i & 511;
        g_h0T[3 * H_ * HPAD + k * HPAD + b] = __float2half(h0[b * H_ + k]);
        g_h1T[k * HPAD + b]                 = __float2half(h0[B_ * H_ + b * H_ + k]);
    }
    if (tid < 4) { g_c0g[tid] = 0; g_c1g[tid] = 0; }
    if (tid == 4) g_cnt1 = 0;
}

__global__ void __launch_bounds__(256) lstm86_prepx(const float* __restrict__ x)
{
    __shared__ __half sm[128 * 136];
    const int t = blockIdx.x, tid = threadIdx.x;
    for (int i = tid; i < B_ * D_; i += 256) {
        int b = i >> 7, d = i & 127;
        sm[d * 136 + b] = __float2half(x[(size_t)b * (T_ * D_) + t * D_ + d]);
    }
    __syncthreads();
    for (int i = tid; i < 128 * 16; i += 256) {
        int d = i >> 4, seg = i & 15;
        *(uint4*)&g_xTT[(size_t)t * D_ * HPAD + d * HPAD + seg * 8] = *(uint4*)&sm[d * 136 + seg * 8];
    }
}

// ---------------- recurrent role (exact R10 = 2178us version) ----------------
template <int LAYER>
__device__ void lstm86_role(int q, const float* __restrict__ c0, char* smem)
{
    constexpr int K  = (LAYER == 0) ? 640 : 1024;
    constexpr int NC = (LAYER == 0) ? 5 : 8;     // 128-k chunks
    const int tid  = threadIdx.x;
    const int warp = tid >> 5, lane = tid & 31;
    const uint32_t sb = (uint32_t)__cvta_generic_to_shared(smem);
    const uint32_t MB = sb + MB_OFF;

    if (tid == 0) {
        #pragma unroll
        for (int st = 0; st < 4; st++) { mbar_init(MB + st * 16, 1); mbar_init(MB + st * 16 + 8, 256); }
        fence_pa();
    }
    // resident weights: [kc64][32 n][144 B]; local n = gate*8 + jj
    {
        const __half* Wg = (LAYER == 0) ? g_W0 : g_W1;
        for (int i = tid; i < (K / 64) * 256; i += 288) {
            int kc = i >> 8, rem = i & 255, n = rem >> 3, sg = rem & 7;
            int ng = (n >> 3) * 512 + q * 8 + (n & 7);
            *(uint4*)(smem + B_OFF + kc * BCHUNK_SZ + n * 144 + sg * 16) =
                *(const uint4*)&Wg[(size_t)ng * K + kc * 64 + sg * 8];
        }
    }
    __syncthreads();   // last full-block sync

    // ================= producer warp (warp 8) =================
    // LAYER 1 chunk order: j=0-3 -> h0 input (ready early); j=4-7 -> self h1(t-1).
    if (warp == 8) {
        if (tid == 256) {
            int igi = 0;
            for (int t = 0; t < T_; t++) {
                for (int i = 0; i < NC; i++) {
                    if (LAYER == 0) {
                        if (i >= 1 && t > 0) wait_cnt(&g_c0g[i - 1], 16u * (unsigned)t);
                    } else {
                        if (i < 4) wait_cnt(&g_c0g[i], 16u * (unsigned)(t + 1));
                        else if (t > 0) wait_cnt(&g_c1g[i - 4], 16u * (unsigned)t);
                    }
                    int st = igi & 3;
                    if (igi >= 4) mbar_wait(MB + st * 16 + 8, (unsigned)((igi - 4) >> 2) & 1);
                    const __half* src;
                    if (LAYER == 0)
                        src = (i == 0) ? g_xTT + (size_t)t * D_ * HPAD
                                       : g_h0T + (size_t)((t + 3) & 3) * H_ * HPAD + (size_t)(i - 1) * 128 * HPAD;
                    else
                        src = (i < 4) ? g_h0T + (size_t)(t & 3) * H_ * HPAD + (size_t)i * 128 * HPAD
                                      : g_h1T + (size_t)t * H_ * HPAD + (size_t)(i - 4) * 128 * HPAD;
                    mbar_expect(MB + st * 16, CHB);
                    bulk_g2s(sb + (uint32_t)st * CHB, src, CHB, MB + st * 16);
                    igi++;
                }
            }
        }
        return;
    }

    // ================= consumer warps (0-7): split-K, m32 x n32 each =================
    const int km  = warp >> 2;        // k-half of each chunk
    const int wm4 = warp & 3;         // m-tile id
    const uint32_t a_krow = (uint32_t)((lane & 7) + ((lane >> 4) & 1) * 8);
    const uint32_t a_col  = (uint32_t)(wm4 * 32 + ((lane >> 3) & 1) * 8);
    const uint32_t b_row  = (uint32_t)(((lane >> 4) & 1) * 8 + (lane & 7));
    const uint32_t b_koff = (uint32_t)(((lane >> 3) & 1) * 8);

    const int rrow0 = wm4 * 32 + (lane >> 2);
    const int jcol  = q * 8 + (lane & 3) * 2;
    float creg[2][2][2];
    if (km == 0) {
        #pragma unroll
        for (int mi = 0; mi < 2; mi++)
            #pragma unroll
            for (int hf = 0; hf < 2; hf++) {
                int r = rrow0 + mi * 16 + hf * 8;
                creg[mi][hf][0] = c0[LAYER * B_ * H_ + (size_t)r * H_ + jcol];
                creg[mi][hf][1] = c0[LAYER * B_ * H_ + (size_t)r * H_ + jcol + 1];
            }
    }

    float* red = (float*)(smem + RED_OFF);
    int cgi = 0;
    for (int t = 0; t < T_; t++) {
        float acc[2][4][4];
        #pragma unroll
        for (int mi = 0; mi < 2; mi++)
            #pragma unroll
            for (int n8 = 0; n8 < 4; n8++)
                #pragma unroll
                for (int r = 0; r < 4; r++) acc[mi][n8][r] = 0.0f;

        for (int j = 0; j < NC; j++) {
            int st = cgi & 3;
            mbar_wait(MB + st * 16, (unsigned)(cgi >> 2) & 1);
            cgi++;
            const uint32_t SA = sb + (uint32_t)st * CHB;
            const int kcb = (LAYER == 0) ? 2 * j : ((j < 4) ? 2 * j : 8 + 2 * (j - 4));
            const uint32_t BC = sb + B_OFF + (uint32_t)(kcb + km) * BCHUNK_SZ;
            #pragma unroll
            for (int kk = 0; kk < 4; kk++) {
                int kke = km * 4 + kk;
                uint32_t a0[4], a1[4], b0[4], b1[4];
                uint32_t krow = (uint32_t)(kke * 16) + a_krow;
                ldsm4t(a0, SA + krow * ROWB + a_col * 2);
                ldsm4t(a1, SA + krow * ROWB + (a_col + 16) * 2);
                uint32_t kb = (uint32_t)kk * 32;
                ldsm4(b0, BC + b_row * 144 + kb + b_koff * 2);
                ldsm4(b1, BC + (b_row + 16) * 144 + kb + b_koff * 2);
                mma_f16(acc[0][0], a0, b0);  mma_f16(acc[0][1], a0, b0 + 2);
                mma_f16(acc[0][2], a0, b1);  mma_f16(acc[0][3], a0, b1 + 2);
                mma_f16(acc[1][0], a1, b0);  mma_f16(acc[1][1], a1, b0 + 2);
                mma_f16(acc[1][2], a1, b1);  mma_f16(acc[1][3], a1, b1 + 2);
            }
            mbar_arrive(MB + st * 16 + 8);
        }

        // ---- split-K reduction: warps 4-7 publish partials ----
        if (km == 1) {
            #pragma unroll
            for (int e = 0; e < 32; e++)
                red[e * 128 + wm4 * 32 + lane] = acc[e >> 4][(e >> 2) & 3][e & 3];
        }
        barc();
        if (km == 0) {
            #pragma unroll
            for (int e = 0; e < 32; e++)
                acc[e >> 4][(e >> 2) & 3][e & 3] += red[e * 128 + wm4 * 32 + lane];

            // ---- epilogue (warps 0-3) ----
            __half* hs = (__half*)(smem + HST_OFF);
            #pragma unroll
            for (int mi = 0; mi < 2; mi++)
                #pragma unroll
                for (int hf = 0; hf < 2; hf++) {
                    int r = rrow0 + mi * 16 + hf * 8;
                    float h2[2];
                    #pragma unroll
                    for (int cs = 0; cs < 2; cs++) {
                        float gi = acc[mi][0][hf * 2 + cs];
                        float gf = acc[mi][1][hf * 2 + cs];
                        float gg = acc[mi][2][hf * 2 + cs];
                        float go = acc[mi][3][hf * 2 + cs];
                        float cn = sigf(gf) * creg[mi][hf][cs] + sigf(gi) * tanhe(gg);
                        creg[mi][hf][cs] = cn;
                        h2[cs] = sigf(go) * tanhe(cn);
                        hs[((lane & 3) * 2 + cs) * HPAD + r] = __float2half(h2[cs]);
                    }
                    if (LAYER == 1) {
                        __half2 p = __floats2half2_rn(h2[0], h2[1]);
                        *(__half2*)(g_h1seq + (size_t)(t + 1) * (B_ * H_) + (size_t)r * H_ + jcol) = p;
                    }
                }
        }
        if (LAYER == 0 && t >= 4 && tid == 0) wait_cnt(&g_cnt1, 64u * (unsigned)(t - 3));  // ring guard
        barc();
        if (tid < 128) {
            int jl = tid >> 4, sg = tid & 15;
            __half* dst = ((LAYER == 0) ? g_h0T + (size_t)(t & 3) * H_ * HPAD
                                        : g_h1T + (size_t)(t + 1) * H_ * HPAD)
                          + (size_t)(q * 8 + jl) * HPAD + sg * 8;
            *(uint4*)dst = *(uint4*)(smem + HST_OFF + jl * ROWB + sg * 16);
        }
        barc();
        if (tid == 0) {
            if (LAYER == 0) arrive_cnt(&g_c0g[q >> 4]);
            else            { arrive_cnt(&g_c1g[q >> 4]); arrive_cnt(&g_cnt1); }
        }
    }
}

// ---------------- output-projection role (fused; polls g_cnt1) ----------------
__device__ void lstm86_out_role(int t, const float* __restrict__ b_out,
                                float* __restrict__ out, char* smem)
{
    const int tid = threadIdx.x;
    if (tid >= 256) return;          // 288-thread block; out path uses 256

    __half* Ws    = (__half*)smem;                           // [128][520]
    __half* Ab    = (__half*)(smem + 128 * 520 * 2);         // 2 x [128][72]
    float*  biasS = (float*)(smem + 128 * 520 * 2 + 2 * 128 * 72 * 2);

    const int warp = tid >> 5, lane = tid & 31;
    const int wm = warp >> 1, wn = warp & 1;

    for (int i = tid; i < 128 * 64; i += 256) {
        int n = i >> 6, v = i & 63;
        *(uint4*)&Ws[n * 520 + v * 8] = *(const uint4*)&g_Wout[n * 512 + v * 8];
    }
    for (int i = tid; i < 128; i += 256) biasS[i] = b_out[i];

    // wait until tick t complete (h1seq[t+1] published via release)
    if (tid == 0) wait_cnt_sleep(&g_cnt1, 64u * (unsigned)(t + 1));
    barc();

    const __half* Asrc = g_h1seq + (size_t)(t + 1) * (B_ * H_);

    float acc[2][8][4];
    #pragma unroll
    for (int mi = 0; mi < 2; mi++)
        #pragma unroll
        for (int ni = 0; ni < 8; ni++)
            #pragma unroll
            for (int r = 0; r < 4; r++) acc[mi][ni][r] = 0.0f;

    auto load_chunk = [&](int c) {
        __half* dst = Ab + (c & 1) * (128 * 72);
        #pragma unroll
        for (int j = 0; j < 4; j++) {
            int i = tid + j * 256;
            int row = i >> 3, seg = i & 7;
            uint32_t sa = (uint32_t)__cvta_generic_to_shared(dst + row * 72 + seg * 8);
            asm volatile("cp.async.cg.shared.global [%0], [%1], 16;"
                         :: "r"(sa), "l"(Asrc + (size_t)row * H_ + c * 64 + seg * 8));
        }
        asm volatile("cp.async.commit_group;");
    };

    load_chunk(0);
    for (int c = 0; c < 8; c++) {
        if (c < 7) { load_chunk(c + 1); asm volatile("cp.async.wait_group 1;"); }
        else       { asm volatile("cp.async.wait_group 0;"); }
        barc();
        const __half* A = Ab + (c & 1) * (128 * 72);
        #pragma unroll
        for (int kk = 0; kk < 4; kk++) {
            uint32_t af[2][4], bf2[8][2];
            #pragma unroll
            for (int mi = 0; mi < 2; mi++) {
                int r = wm * 32 + mi * 16 + (lane >> 2);
                int ci = kk * 16 + (lane & 3) * 2;
                af[mi][0] = *(const uint32_t*)&A[r * 72 + ci];
                af[mi][1] = *(const uint32_t*)&A[(r + 8) * 72 + ci];
                af[mi][2] = *(const uint32_t*)&A[r * 72 + ci + 8];
                af[mi][3] = *(const uint32_t*)&A[(r + 8) * 72 + ci + 8];
            }
            #pragma unroll
            for (int ni = 0; ni < 8; ni++) {
                int n  = wn * 64 + ni * 8 + (lane >> 2);
                int kg = c * 64 + kk * 16 + (lane & 3) * 2;
                bf2[ni][0] = *(const uint32_t*)&Ws[n * 520 + kg];
                bf2[ni][1] = *(const uint32_t*)&Ws[n * 520 + kg + 8];
            }
            #pragma unroll
            for (int mi = 0; mi < 2; mi++)
                #pragma unroll
                for (int ni = 0; ni < 8; ni++)
                    mma_f16(acc[mi][ni], af[mi], bf2[ni]);
        }
        barc();
    }

    #pragma unroll
    for (int mi = 0; mi < 2; mi++)
        #pragma unroll
        for (int ni = 0; ni < 8; ni++) {
            int r  = wm * 32 + mi * 16 + (lane >> 2);
            int co = wn * 64 + ni * 8 + (lane & 3) * 2;
            float b0 = biasS[co], b1 = biasS[co + 1];
            size_t o0 = (size_t)r * (T_ * O_) + (size_t)t * O_ + co;
            size_t o1 = (size_t)(r + 8) * (T_ * O_) + (size_t)t * O_ + co;
            *(float2*)&out[o0] = make_float2(acc[mi][ni][0] + b0, acc[mi][ni][1] + b1);
            *(float2*)&out[o1] = make_float2(acc[mi][ni][2] + b0, acc[mi][ni][3] + b1);
        }
}

__global__ void __launch_bounds__(288, 1) lstm86_recur(const float* __restrict__ c0,
                                                       const float* __restrict__ b_out,
                                                       float* __restrict__ out)
{
    extern __shared__ char smem[];
    if (blockIdx.x < NL)            lstm86_role<0>(blockIdx.x, c0, smem);
    else if (blockIdx.x < NCTA)     lstm86_role<1>(blockIdx.x - NL, c0, smem);
    else                            lstm86_out_role(blockIdx.x - NCTA, b_out, out, smem);
}

extern "C" void kernel_launch(void* const* d_in, const int* in_sizes, int n_in,
                              void* d_out, int out_size)
{
    const float* x    = (const float*)d_in[0];
    const float* h0   = (const float*)d_in[1];
    const float* c0   = (const float*)d_in[2];
    const float* wih0 = (const float*)d_in[3];
    const float* whh0 = (const float*)d_in[4];
    const float* wih1 = (const float*)d_in[5];
    const float* whh1 = (const float*)d_in[6];
    const float* wout = (const float*)d_in[7];
    const float* bout = (const float*)d_in[8];

    cudaFuncSetAttribute(lstm86_recur, cudaFuncAttributeMaxDynamicSharedMemorySize, SMEM_LSTM);

    lstm86_prep<<<1024, 256>>>(h0, wih0, whh0, wih1, whh1, wout);
    lstm86_prepx<<<T_, 256>>>(x);
    lstm86_recur<<<NCTA + T_, 288, SMEM_LSTM>>>(c0, bout, (float*)d_out);
}